// round 13
// baseline (speedup 1.0000x reference)
#include <cuda_runtime.h>

#define NHEADS 8
#define HDIM   64
#define TNUM   10
#define QDIM   256
#define NCOLS  80        // NHEADS * TNUM
#define NBATCH 131072

#define GPITCH 12            // per-head group pitch (10 used + 2 pad), 4-aligned
#define MPITCH 96            // 8 groups * 12 floats (384B/row)
#define KT     64            // k-tile held in shared
#define NKT    (QDIM / KT)   // 4
#define BROWS  128           // rows per block (4 per thread)
#define TPB    256

// Precomputed fused projection matrix in grouped layout:
// M_g[k][h*GPITCH + t],  scores[h,n,t] = sum_k X[n,k] * M[k][h*GPITCH+t]
__device__ float M_g[QDIM * MPITCH];

__global__ void precompute_M(const float* __restrict__ embed,
                             const float* __restrict__ Wq,
                             const float* __restrict__ Wk) {
    const int col = blockIdx.x;          // 0..79
    const int h = col / TNUM;
    const int t = col % TNUM;
    __shared__ float kv[HDIM];
    const int tid = threadIdx.x;         // 0..255
    if (tid < HDIM) {
        const int e = h * HDIM + tid;
        float s = 0.f;
        #pragma unroll
        for (int d = 0; d < HDIM; ++d)
            s += tanhf(embed[t * HDIM + d]) * Wk[e * HDIM + d];
        kv[tid] = s;
    }
    __syncthreads();
    float s = 0.f;
    #pragma unroll
    for (int dd = 0; dd < HDIM; ++dd)
        s += Wq[(h * HDIM + dd) * QDIM + tid] * kv[dd];
    M_g[tid * MPITCH + h * GPITCH + t] = s * 0.125f;
}

// ---- packed f32x2 helpers (FFMA2: 2x fp32 FMA throughput on sm_103a) ----
__device__ __forceinline__ unsigned long long splat2(float x) {
    unsigned long long r;
    asm("mov.b64 %0, {%1, %1};" : "=l"(r) : "r"(__float_as_uint(x)));
    return r;
}
__device__ __forceinline__ void fma2(unsigned long long& d,
                                     unsigned long long a,
                                     unsigned long long b) {
    asm("fma.rn.f32x2 %0, %1, %2, %0;" : "+l"(d) : "l"(a), "l"(b));
}
__device__ __forceinline__ float2 unpack2(unsigned long long v) {
    float lo, hi;
    asm("mov.b64 {%0, %1}, %2;" : "=f"(lo), "=f"(hi) : "l"(v));
    return make_float2(lo, hi);
}

__global__ __launch_bounds__(TPB, 2)
void fused_attn(const float* __restrict__ X,
                const float* __restrict__ embed,
                float* __restrict__ style,   // [N][512]
                float* __restrict__ attn)    // [8][N][10]
{
    // One k-tile of M: 64 x 96 floats = 24KB. No A staging:
    // 8 lanes (one per head) share each X row -> LDG warp-broadcast + L1 reuse.
    __shared__ __align__(16) float M_sh[KT][MPITCH];
    __shared__ __align__(16) float kr_sh[TNUM * HDIM];

    const int tid = threadIdx.x;
    const int rg = tid >> 3;     // 0..31 : row slot
    const int cg = tid & 7;      // 0..7  : head
    const int rowBase = blockIdx.x * BROWS;

    for (int i = tid; i < TNUM * HDIM; i += TPB)
        kr_sh[i] = tanhf(embed[i]);

    // 4 row-streams per thread: rows rg, rg+32, rg+64, rg+96
    unsigned long long acc[4][5];
    #pragma unroll
    for (int r = 0; r < 4; ++r)
        #pragma unroll
        for (int j = 0; j < 5; ++j)
            acc[r][j] = 0ull;

    const float* xb = X + ((size_t)rowBase + rg) * QDIM;

    for (int t = 0; t < NKT; ++t) {
        __syncthreads();
        // cooperative M tile copy: 1536 float4, 6 per thread, coalesced
        {
            const float4* src = (const float4*)(M_g + t * KT * MPITCH);
            float4* dst = (float4*)&M_sh[0][0];
            #pragma unroll
            for (int j = 0; j < 6; ++j)
                dst[tid + TPB * j] = src[tid + TPB * j];
        }
        __syncthreads();

        const float* xt = xb + t * KT;

        #pragma unroll 2
        for (int k4 = 0; k4 < KT / 4; ++k4) {
            // 4 rows x 4 k values (LDG.128 broadcast across the 8 head-lanes)
            float4 a[4];
            #pragma unroll
            for (int r = 0; r < 4; ++r)
                a[r] = *(const float4*)(xt + (size_t)r * 32 * QDIM + k4 * 4);

            #pragma unroll
            for (int j = 0; j < 4; ++j) {
                const float* mrow = &M_sh[k4 * 4 + j][cg * GPITCH];
                const ulonglong2 m01 = *(const ulonglong2*)mrow;
                const ulonglong2 m23 = *(const ulonglong2*)(mrow + 4);
                const unsigned long long m4 = *(const unsigned long long*)(mrow + 8);
                #pragma unroll
                for (int r = 0; r < 4; ++r) {
                    const unsigned long long s = splat2(((const float*)&a[r])[j]);
                    fma2(acc[r][0], s, m01.x);
                    fma2(acc[r][1], s, m01.y);
                    fma2(acc[r][2], s, m23.x);
                    fma2(acc[r][3], s, m23.y);
                    fma2(acc[r][4], s, m4);
                }
            }
        }
    }

    // ---- epilogue, one row at a time (register-lean) ----
    #pragma unroll
    for (int r = 0; r < 4; ++r) {
        const size_t n = (size_t)rowBase + rg + r * 32;

        float s10[10];
        #pragma unroll
        for (int j = 0; j < 5; ++j) {
            const float2 f = unpack2(acc[r][j]);
            s10[2 * j]     = f.x;
            s10[2 * j + 1] = f.y;
        }

        // attn_score: [h][n][t], h == cg
        float2* ap = (float2*)(attn + (size_t)cg * NBATCH * TNUM + n * TNUM);
        #pragma unroll
        for (int j = 0; j < 5; ++j)
            ap[j] = make_float2(s10[2 * j], s10[2 * j + 1]);

        // style: out[n, cg*64 + d] = sum_t s10[t] * kr[t][d]
        float* outp = style + n * 512 + cg * 64;
        #pragma unroll
        for (int ch = 0; ch < 4; ++ch) {        // 16-float chunks of d
            unsigned long long o[8] = {0ull,0ull,0ull,0ull,0ull,0ull,0ull,0ull};
            #pragma unroll
            for (int t = 0; t < TNUM; ++t) {
                const unsigned long long sv = splat2(s10[t]);
                const float* kp = kr_sh + t * HDIM + ch * 16;
                const ulonglong2 ka = *(const ulonglong2*)kp;
                const ulonglong2 kb = *(const ulonglong2*)(kp + 4);
                const ulonglong2 kc = *(const ulonglong2*)(kp + 8);
                const ulonglong2 kd = *(const ulonglong2*)(kp + 12);
                fma2(o[0], sv, ka.x);
                fma2(o[1], sv, ka.y);
                fma2(o[2], sv, kb.x);
                fma2(o[3], sv, kb.y);
                fma2(o[4], sv, kc.x);
                fma2(o[5], sv, kc.y);
                fma2(o[6], sv, kd.x);
                fma2(o[7], sv, kd.y);
            }
            #pragma unroll
            for (int q = 0; q < 4; ++q) {
                const float2 f0 = unpack2(o[2 * q]);
                const float2 f1 = unpack2(o[2 * q + 1]);
                *(float4*)(outp + ch * 16 + q * 4) =
                    make_float4(f0.x, f0.y, f1.x, f1.y);
            }
        }
    }
}

extern "C" void kernel_launch(void* const* d_in, const int* in_sizes, int n_in,
                              void* d_out, int out_size) {
    (void)in_sizes; (void)n_in; (void)out_size;
    const float* X     = (const float*)d_in[0];
    const float* embed = (const float*)d_in[1];
    const float* Wq    = (const float*)d_in[2];
    const float* Wk    = (const float*)d_in[3];

    float* style = (float*)d_out;                              // N*512 floats
    float* attn  = (float*)d_out + (size_t)NBATCH * 512;       // 8*N*10 floats

    precompute_M<<<NCOLS, 256>>>(embed, Wq, Wk);
    fused_attn<<<NBATCH / BROWS, TPB>>>(X, embed, style, attn);
}

// round 14
// speedup vs baseline: 1.4100x; 1.4100x over previous
#include <cuda_runtime.h>

#define NHEADS 8
#define HDIM   64
#define TNUM   10
#define QDIM   256
#define NCOLS  80        // NHEADS * TNUM
#define NBATCH 131072

#define GPITCH 12            // per-head group pitch (10 used + 2 pad), 4-aligned
#define MPITCH 96            // 8 groups * 12 floats (384B/row)
#define KT     128           // k-tile of M held in shared (48KB)
#define NKT    (QDIM / KT)   // 2
#define BROWS  64            // rows per block (2 per thread)
#define TPB    256

#define KR_ELEMS (TNUM * HDIM)
#define SMEM_BYTES ((KT * MPITCH + KR_ELEMS) * 4)

// Precomputed fused projection matrix in grouped layout:
// M_g[k][h*GPITCH + t],  scores[h,n,t] = sum_k X[n,k] * M[k][h*GPITCH+t]
__device__ float M_g[QDIM * MPITCH];

__global__ void precompute_M(const float* __restrict__ embed,
                             const float* __restrict__ Wq,
                             const float* __restrict__ Wk) {
    const int col = blockIdx.x;          // 0..79
    const int h = col / TNUM;
    const int t = col % TNUM;
    __shared__ float kv[HDIM];
    const int tid = threadIdx.x;         // 0..255
    if (tid < HDIM) {
        const int e = h * HDIM + tid;
        float s = 0.f;
        #pragma unroll
        for (int d = 0; d < HDIM; ++d)
            s += tanhf(embed[t * HDIM + d]) * Wk[e * HDIM + d];
        kv[tid] = s;
    }
    __syncthreads();
    float s = 0.f;
    #pragma unroll
    for (int dd = 0; dd < HDIM; ++dd)
        s += Wq[(h * HDIM + dd) * QDIM + tid] * kv[dd];
    M_g[tid * MPITCH + h * GPITCH + t] = s * 0.125f;
}

// ---- packed f32x2 helpers (FFMA2: 2x fp32 FMA throughput on sm_103a) ----
__device__ __forceinline__ unsigned long long splat2(float x) {
    unsigned long long r;
    asm("mov.b64 %0, {%1, %1};" : "=l"(r) : "r"(__float_as_uint(x)));
    return r;
}
__device__ __forceinline__ void fma2(unsigned long long& d,
                                     unsigned long long a,
                                     unsigned long long b) {
    asm("fma.rn.f32x2 %0, %1, %2, %0;" : "+l"(d) : "l"(a), "l"(b));
}
__device__ __forceinline__ float2 unpack2(unsigned long long v) {
    float lo, hi;
    asm("mov.b64 {%0, %1}, %2;" : "=f"(lo), "=f"(hi) : "l"(v));
    return make_float2(lo, hi);
}

__global__ __launch_bounds__(TPB, 3)
void fused_attn(const float* __restrict__ X,
                const float* __restrict__ embed,
                float* __restrict__ style,   // [N][512]
                float* __restrict__ attn)    // [8][N][10]
{
    extern __shared__ __align__(16) float smem_dyn[];
    float* M_sh  = smem_dyn;                 // [KT][MPITCH]  48KB
    float* kr_sh = smem_dyn + KT * MPITCH;   // [640]

    const int tid = threadIdx.x;
    const int rg = tid >> 3;     // 0..31 : row slot
    const int cg = tid & 7;      // 0..7  : head
    const int rowBase = blockIdx.x * BROWS;
    const size_t n0 = (size_t)rowBase + rg;        // row A
    const size_t n1 = (size_t)rowBase + rg + 32;   // row B

    for (int i = tid; i < KR_ELEMS; i += TPB)
        kr_sh[i] = tanhf(embed[i]);

    unsigned long long acc0[5], acc1[5];   // 5 col-pairs (10 cols) per row
    #pragma unroll
    for (int j = 0; j < 5; ++j) { acc0[j] = 0ull; acc1[j] = 0ull; }

    const float* x0 = X + n0 * QDIM;
    const float* x1 = X + n1 * QDIM;

    // software pipeline: prefetch k4-group 0 before the first M-tile barrier
    float4 a0c = *(const float4*)(x0);
    float4 a1c = *(const float4*)(x1);

    for (int t = 0; t < NKT; ++t) {
        __syncthreads();
        // cooperative M tile copy: KT*MPITCH floats = 3072 float4, 12/thread
        {
            const float4* src = (const float4*)(M_g + t * KT * MPITCH);
            float4* dst = (float4*)M_sh;
            #pragma unroll
            for (int j = 0; j < 12; ++j)
                dst[tid + TPB * j] = src[tid + TPB * j];
        }
        __syncthreads();

        #pragma unroll 2
        for (int j = 0; j < KT / 4; ++j) {
            // prefetch next k4 group (linear across tiles; clamp at the end)
            const int g = t * (KT / 4) + j;
            const int gn = (g + 1 < QDIM / 4) ? g + 1 : g;
            const float4 a0n = *(const float4*)(x0 + gn * 4);
            const float4 a1n = *(const float4*)(x1 + gn * 4);

            #pragma unroll
            for (int jj = 0; jj < 4; ++jj) {
                const float* mrow = M_sh + (j * 4 + jj) * MPITCH + cg * GPITCH;
                const ulonglong2 m01 = *(const ulonglong2*)mrow;
                const ulonglong2 m23 = *(const ulonglong2*)(mrow + 4);
                const unsigned long long m4 = *(const unsigned long long*)(mrow + 8);
                const unsigned long long s0 = splat2(((const float*)&a0c)[jj]);
                fma2(acc0[0], s0, m01.x);
                fma2(acc0[1], s0, m01.y);
                fma2(acc0[2], s0, m23.x);
                fma2(acc0[3], s0, m23.y);
                fma2(acc0[4], s0, m4);
                const unsigned long long s1 = splat2(((const float*)&a1c)[jj]);
                fma2(acc1[0], s1, m01.x);
                fma2(acc1[1], s1, m01.y);
                fma2(acc1[2], s1, m23.x);
                fma2(acc1[3], s1, m23.y);
                fma2(acc1[4], s1, m4);
            }
            a0c = a0n;
            a1c = a1n;
        }
    }

    // ---- epilogue, one row at a time (register-lean) ----
    #pragma unroll
    for (int r = 0; r < 2; ++r) {
        const unsigned long long* acc = r ? acc1 : acc0;
        const size_t n = r ? n1 : n0;

        float s10[10];
        #pragma unroll
        for (int j = 0; j < 5; ++j) {
            const float2 f = unpack2(acc[j]);
            s10[2 * j]     = f.x;
            s10[2 * j + 1] = f.y;
        }

        // attn_score: [h][n][t], h == cg
        float2* ap = (float2*)(attn + (size_t)cg * NBATCH * TNUM + n * TNUM);
        #pragma unroll
        for (int j = 0; j < 5; ++j)
            ap[j] = make_float2(s10[2 * j], s10[2 * j + 1]);

        // style: out[n, cg*64 + d] = sum_t s10[t] * kr[t][d]
        float* outp = style + n * 512 + cg * 64;
        #pragma unroll
        for (int ch = 0; ch < 4; ++ch) {        // 16-float chunks of d
            unsigned long long o[8] = {0ull,0ull,0ull,0ull,0ull,0ull,0ull,0ull};
            #pragma unroll
            for (int t = 0; t < TNUM; ++t) {
                const unsigned long long sv = splat2(s10[t]);
                const float* kp = kr_sh + t * HDIM + ch * 16;
                const ulonglong2 ka = *(const ulonglong2*)kp;
                const ulonglong2 kb = *(const ulonglong2*)(kp + 4);
                const ulonglong2 kc = *(const ulonglong2*)(kp + 8);
                const ulonglong2 kd = *(const ulonglong2*)(kp + 12);
                fma2(o[0], sv, ka.x);
                fma2(o[1], sv, ka.y);
                fma2(o[2], sv, kb.x);
                fma2(o[3], sv, kb.y);
                fma2(o[4], sv, kc.x);
                fma2(o[5], sv, kc.y);
                fma2(o[6], sv, kd.x);
                fma2(o[7], sv, kd.y);
            }
            #pragma unroll
            for (int q = 0; q < 4; ++q) {
                const float2 f0 = unpack2(o[2 * q]);
                const float2 f1 = unpack2(o[2 * q + 1]);
                *(float4*)(outp + ch * 16 + q * 4) =
                    make_float4(f0.x, f0.y, f1.x, f1.y);
            }
        }
    }
}

extern "C" void kernel_launch(void* const* d_in, const int* in_sizes, int n_in,
                              void* d_out, int out_size) {
    (void)in_sizes; (void)n_in; (void)out_size;
    const float* X     = (const float*)d_in[0];
    const float* embed = (const float*)d_in[1];
    const float* Wq    = (const float*)d_in[2];
    const float* Wk    = (const float*)d_in[3];

    float* style = (float*)d_out;                              // N*512 floats
    float* attn  = (float*)d_out + (size_t)NBATCH * 512;       // 8*N*10 floats

    static int smem_set = 0;
    if (!smem_set) {
        cudaFuncSetAttribute(fused_attn,
                             cudaFuncAttributeMaxDynamicSharedMemorySize,
                             SMEM_BYTES);
        smem_set = 1;
    }

    precompute_M<<<NCOLS, 256>>>(embed, Wq, Wk);
    fused_attn<<<NBATCH / BROWS, TPB, SMEM_BYTES>>>(X, embed, style, attn);
}